// round 17
// baseline (speedup 1.0000x reference)
#include <cuda_runtime.h>
#include <cuda_bf16.h>
#include <cstdint>

#define N_NODES 150000
#define N_EDGES 2400000
#define D 128
#define ROWS_PER_BLK 64
#define N_TILES ((N_NODES + ROWS_PER_BLK - 1) / ROWS_PER_BLK)   // 2344
#define DENSE_GRID 148
#define DSTRIDE 136            // bf16 row stride: 272B -> 4-bank skew, conflict-free frags

#define SCAN_TILE 1024
#define SCAN_BLOCKS ((N_NODES + SCAN_TILE - 1) / SCAN_TILE)   // 147  (<= 148 SMs: all resident)
#define PREP_BLOCKS 64
#define HIST_BLOCKS ((N_EDGES + 255) / 256)

// ------------------------- device scratch (no runtime alloc) -------------------------
__device__ float g_side[(size_t)N_NODES * D];     // 76.8 MB
__device__ int   g_cnt[N_NODES];                  // zero at entry (zero-init / re-zeroed by dense)
__device__ int   g_start[N_NODES];
__device__ int   g_cursor[N_NODES];
__device__ unsigned long long g_scanstate[SCAN_BLOCKS];  // packed flag<<32 | value; 0 at entry
__device__ int2  g_edge_s[N_EDGES];               // CSR-ordered (col, val_bits)
// W^T split-bf16, padded [n][k] layout (n*DSTRIDE + k): [Wg_hi][Wg_lo][Wbi_hi][Wbi_lo]
__device__ __align__(16) __nv_bfloat16 g_W[4 * 128 * DSTRIDE];

// ------------------------- memory helpers -------------------------
__device__ __forceinline__ int2 ldcs_int2(const int2* p) {
    int2 v;
    asm volatile("ld.global.cs.v2.b32 {%0,%1}, [%2];" : "=r"(v.x), "=r"(v.y) : "l"(p));
    return v;
}
__device__ __forceinline__ void stcs_int2(int2* p, int2 v) {
    asm volatile("st.global.cs.v2.b32 [%0], {%1,%2};" :: "l"(p), "r"(v.x), "r"(v.y) : "memory");
}
__device__ __forceinline__ void stcs_float4(float4* p, float4 v) {
    asm volatile("st.global.cs.v4.f32 [%0], {%1,%2,%3,%4};"
                 :: "l"(p), "f"(v.x), "f"(v.y), "f"(v.z), "f"(v.w) : "memory");
}
__device__ __forceinline__ void st_release_u64(unsigned long long* p, unsigned long long v) {
    asm volatile("st.release.gpu.global.u64 [%0], %1;" :: "l"(p), "l"(v) : "memory");
}
__device__ __forceinline__ unsigned long long ld_acquire_u64(const unsigned long long* p) {
    unsigned long long v;
    asm volatile("ld.acquire.gpu.global.u64 %0, [%1];" : "=l"(v) : "l"(p) : "memory");
    return v;
}

// ------------------------- kernel 1: hist + W prep (independent work, one launch) -------------------------
__global__ void histprep_kernel(const int* __restrict__ erow,
                                const float* __restrict__ wgc,
                                const float* __restrict__ wbi) {
    int b = blockIdx.x;
    if (b < PREP_BLOCKS) {
        int i = b * 256 + threadIdx.x;
        if (i < 128 * 128) {
            int k = i >> 7, n = i & 127;
            float vg = wgc[i];                     // wgc[k][n]
            float vb = wbi[i];
            __nv_bfloat16 gh = __float2bfloat16(vg);
            __nv_bfloat16 gl = __float2bfloat16(vg - __bfloat162float(gh));
            __nv_bfloat16 bh = __float2bfloat16(vb);
            __nv_bfloat16 bl = __float2bfloat16(vb - __bfloat162float(bh));
            int off = n * DSTRIDE + k;             // [n][k]
            g_W[off] = gh;
            g_W[128 * DSTRIDE + off] = gl;
            g_W[2 * 128 * DSTRIDE + off] = bh;
            g_W[3 * 128 * DSTRIDE + off] = bl;
        }
    } else {
        int e = (b - PREP_BLOCKS) * 256 + threadIdx.x;
        if (e < N_EDGES) atomicAdd(&g_cnt[erow[e]], 1);
    }
}

// ------------------------- kernel 2: single-pass decoupled-lookback scan -------------------------
// 147 blocks, all resident -> spin-wait is deadlock-free. Writes g_start and g_cursor.
__global__ __launch_bounds__(256)
void scan_kernel() {
    __shared__ int sh[256];
    __shared__ int s_base;
    const int t = threadIdx.x;
    const int b = blockIdx.x;
    const int base_i = b * SCAN_TILE + t * 4;

    int v[4];
#pragma unroll
    for (int j = 0; j < 4; j++)
        v[j] = (base_i + j < N_NODES) ? g_cnt[base_i + j] : 0;
    int s = v[0] + v[1] + v[2] + v[3];
    sh[t] = s;
    __syncthreads();
#pragma unroll
    for (int off = 1; off < 256; off <<= 1) {
        int x = (t >= off) ? sh[t - off] : 0;
        __syncthreads();
        sh[t] += x;
        __syncthreads();
    }
    const int aggregate = sh[255];
    const int local_excl = sh[t] - s;

    // publish aggregate (block 0 publishes its inclusive immediately)
    if (t == 0) {
        if (b == 0) st_release_u64(&g_scanstate[0], (2ULL << 32) | (unsigned)aggregate);
        else        st_release_u64(&g_scanstate[b], (1ULL << 32) | (unsigned)aggregate);
    }

    // lookback: warp 0 walks predecessors, 32 at a time
    if (b == 0) {
        if (t == 0) s_base = 0;
    } else if (t < 32) {
        int running = 0;
        int winStart = b - 1;
        while (true) {
            int myIdx = winStart - t;
            unsigned flag;
            int val;
            if (myIdx >= 0) {
                unsigned long long st;
                do { st = ld_acquire_u64(&g_scanstate[myIdx]); } while ((st >> 32) == 0);
                flag = (unsigned)(st >> 32);
                val = (int)(unsigned)st;
            } else {
                flag = 2; val = 0;    // beyond block 0: terminates search with 0 contribution
            }
            unsigned mask = __ballot_sync(0xffffffffu, flag == 2);
            if (mask) {
                int lt = __ffs(mask) - 1;         // nearest predecessor with inclusive
                int contrib = (t <= lt) ? val : 0; // lanes < lt: aggregates; lane lt: inclusive
#pragma unroll
                for (int m = 16; m >= 1; m >>= 1)
                    contrib += __shfl_xor_sync(0xffffffffu, contrib, m);
                running += contrib;
                break;
            } else {                               // whole window holds aggregates (flag 1)
                int contrib = val;
#pragma unroll
                for (int m = 16; m >= 1; m >>= 1)
                    contrib += __shfl_xor_sync(0xffffffffu, contrib, m);
                running += contrib;
                winStart -= 32;
            }
        }
        if (t == 0) s_base = running;
    }
    __syncthreads();
    const int base = s_base;

    // publish inclusive
    if (t == 0 && b > 0)
        st_release_u64(&g_scanstate[b], (2ULL << 32) | (unsigned)(base + aggregate));

    // write outputs
    int run = base + local_excl;
#pragma unroll
    for (int j = 0; j < 4; j++) {
        if (base_i + j < N_NODES) { g_start[base_i + j] = run; g_cursor[base_i + j] = run; }
        run += v[j];
    }
}

// ------------------------- kernel 3: fill (scatter edges into CSR order) -------------------------
__global__ void fill_kernel(const int* __restrict__ erow,
                            const int* __restrict__ ecol,
                            const float* __restrict__ eval) {
    int e = blockIdx.x * blockDim.x + threadIdx.x;
    if (e < N_EDGES) {
        int r = erow[e];
        int pos = atomicAdd(&g_cursor[r], 1);
        stcs_int2(&g_edge_s[pos], make_int2(ecol[e], __float_as_int(eval[e])));
    }
}

// ------------------------- kernel 4: SpMM, warp per row -------------------------
__global__ __launch_bounds__(256)
void spmm_csr_kernel(const float* __restrict__ ego) {
    int gw = (blockIdx.x * blockDim.x + threadIdx.x) >> 5;
    int lane = threadIdx.x & 31;
    if (gw >= N_NODES) return;
    int start = g_start[gw];
    int end = start + g_cnt[gw];
    const float4* ego4 = (const float4*)ego;
    float4 acc = make_float4(0.f, 0.f, 0.f, 0.f);
    int i = start;
    for (; i + 3 < end; i += 4) {
        int2 e0 = ldcs_int2(&g_edge_s[i]);
        int2 e1 = ldcs_int2(&g_edge_s[i + 1]);
        int2 e2 = ldcs_int2(&g_edge_s[i + 2]);
        int2 e3 = ldcs_int2(&g_edge_s[i + 3]);
        float4 m0 = ego4[(size_t)e0.x * 32 + lane];
        float4 m1 = ego4[(size_t)e1.x * 32 + lane];
        float4 m2 = ego4[(size_t)e2.x * 32 + lane];
        float4 m3 = ego4[(size_t)e3.x * 32 + lane];
        float v0 = __int_as_float(e0.y), v1 = __int_as_float(e1.y);
        float v2 = __int_as_float(e2.y), v3 = __int_as_float(e3.y);
        acc.x = fmaf(v0, m0.x, acc.x); acc.y = fmaf(v0, m0.y, acc.y);
        acc.z = fmaf(v0, m0.z, acc.z); acc.w = fmaf(v0, m0.w, acc.w);
        acc.x = fmaf(v1, m1.x, acc.x); acc.y = fmaf(v1, m1.y, acc.y);
        acc.z = fmaf(v1, m1.z, acc.z); acc.w = fmaf(v1, m1.w, acc.w);
        acc.x = fmaf(v2, m2.x, acc.x); acc.y = fmaf(v2, m2.y, acc.y);
        acc.z = fmaf(v2, m2.z, acc.z); acc.w = fmaf(v2, m2.w, acc.w);
        acc.x = fmaf(v3, m3.x, acc.x); acc.y = fmaf(v3, m3.y, acc.y);
        acc.z = fmaf(v3, m3.z, acc.z); acc.w = fmaf(v3, m3.w, acc.w);
    }
    for (; i < end; i++) {
        int2 e0 = ldcs_int2(&g_edge_s[i]);
        float v0 = __int_as_float(e0.y);
        float4 m0 = ego4[(size_t)e0.x * 32 + lane];
        acc.x = fmaf(v0, m0.x, acc.x); acc.y = fmaf(v0, m0.y, acc.y);
        acc.z = fmaf(v0, m0.z, acc.z); acc.w = fmaf(v0, m0.w, acc.w);
    }
    stcs_float4(&reinterpret_cast<float4*>(g_side)[(size_t)gw * 32 + lane], acc);
}

// ------------------------- kernel 5: persistent dense mma.sync bf16-split -------------------------
#define A_SHI 0
#define A_SLO (64 * DSTRIDE)
#define A_BHI (2 * 64 * DSTRIDE)
#define A_BLO (3 * 64 * DSTRIDE)
#define W_OFF (4 * 64 * DSTRIDE)
#define SMEM_BF16 (W_OFF + 4 * 128 * DSTRIDE)
#define FBIAS_BYTE (SMEM_BF16 * 2)
#define SQ_BYTE (FBIAS_BYTE + 1024)
#define DENSE_SMEM (SQ_BYTE + 512)         // ~210 KB

__device__ __forceinline__ void mma_bf16(float* c, const uint32_t* a, const uint32_t* b) {
    asm volatile("mma.sync.aligned.m16n8k16.row.col.f32.bf16.bf16.f32 "
                 "{%0,%1,%2,%3}, {%4,%5,%6,%7}, {%8,%9}, {%0,%1,%2,%3};"
                 : "+f"(c[0]), "+f"(c[1]), "+f"(c[2]), "+f"(c[3])
                 : "r"(a[0]), "r"(a[1]), "r"(a[2]), "r"(a[3]), "r"(b[0]), "r"(b[1]));
}

__device__ __forceinline__ uint32_t pack_bf16x2(float a, float b) {
    __nv_bfloat162 t;
    t.x = __float2bfloat16(a);
    t.y = __float2bfloat16(b);
    return *reinterpret_cast<uint32_t*>(&t);
}

__global__ __launch_bounds__(256, 1)
void dense_mma_kernel(const float* __restrict__ ego,
                      const float* __restrict__ bgc,
                      const float* __restrict__ bbi,
                      float* __restrict__ out) {
    extern __shared__ __nv_bfloat16 sm[];
    float* fbias = (float*)((char*)sm + FBIAS_BYTE);   // [0:128) bgc, [128:256) bbi
    float* sqbuf = (float*)((char*)sm + SQ_BYTE);      // [2][64]

    const int tid = threadIdx.x;
    const int w = tid >> 5, lane = tid & 31;
    const int mt = w >> 1;            // m-tile 0..3 (16 rows each)
    const int ch = w & 1;             // col half 0..1 (64 cols)
    const int g = lane >> 2, tig = lane & 3;
    const int arow = mt * 16 + g;

    // re-zero cnt + scan state for the NEXT kernel_launch invocation (all readers done;
    // this kernel is last in the launch sequence). First-ever call relies on static zero-init.
    {
        for (int i = blockIdx.x * 256 + tid; i < N_NODES / 4; i += DENSE_GRID * 256)
            reinterpret_cast<int4*>(g_cnt)[i] = make_int4(0, 0, 0, 0);
        for (int i = blockIdx.x * 256 + tid; i < SCAN_BLOCKS; i += DENSE_GRID * 256)
            g_scanstate[i] = 0ULL;
    }

    // one-time: copy prepped W (139,264 B) + bias into smem
    {
        const float4* src = (const float4*)g_W;
        float4* dst = (float4*)(sm + W_OFF);
        for (int i = tid; i < (4 * 128 * DSTRIDE) / 8; i += 256) dst[i] = src[i];
    }
    if (tid < 128) fbias[tid] = bgc[tid];
    else fbias[tid] = bbi[tid - 128];

    const __nv_bfloat16* wGh = sm + W_OFF;
    const __nv_bfloat16* wGl = wGh + 128 * DSTRIDE;
    const __nv_bfloat16* wBh = wGl + 128 * DSTRIDE;
    const __nv_bfloat16* wBl = wBh + 128 * DSTRIDE;

    for (int tile = blockIdx.x; tile < N_TILES; tile += DENSE_GRID) {
        const long row0 = (long)tile * ROWS_PER_BLK;

        // stage A tiles: side hi/lo and (ego*side) hi/lo
        for (int i = tid; i < ROWS_PER_BLK * 32; i += 256) {
            int r = i >> 5, c4 = i & 31;
            long gr = row0 + r;
            float4 s4 = make_float4(0.f, 0.f, 0.f, 0.f);
            float4 b4 = s4;
            if (gr < N_NODES) {
                s4 = reinterpret_cast<const float4*>(g_side + gr * D)[c4];
                float4 e4 = reinterpret_cast<const float4*>(ego + gr * D)[c4];
                b4 = make_float4(s4.x * e4.x, s4.y * e4.y, s4.z * e4.z, s4.w * e4.w);
            }
            int off = r * DSTRIDE + c4 * 4;   // bf16 index, 8B aligned
            {
                uint32_t h0 = pack_bf16x2(s4.x, s4.y), h1 = pack_bf16x2(s4.z, s4.w);
                float r0 = s4.x - __bfloat162float(__float2bfloat16(s4.x));
                float r1 = s4.y - __bfloat162float(__float2bfloat16(s4.y));
                float r2 = s4.z - __bfloat162float(__float2bfloat16(s4.z));
                float r3 = s4.w - __bfloat162float(__float2bfloat16(s4.w));
                uint32_t l0 = pack_bf16x2(r0, r1), l1 = pack_bf16x2(r2, r3);
                *reinterpret_cast<uint2*>(sm + A_SHI + off) = make_uint2(h0, h1);
                *reinterpret_cast<uint2*>(sm + A_SLO + off) = make_uint2(l0, l1);
            }
            {
                uint32_t h0 = pack_bf16x2(b4.x, b4.y), h1 = pack_bf16x2(b4.z, b4.w);
                float r0 = b4.x - __bfloat162float(__float2bfloat16(b4.x));
                float r1 = b4.y - __bfloat162float(__float2bfloat16(b4.y));
                float r2 = b4.z - __bfloat162float(__float2bfloat16(b4.z));
                float r3 = b4.w - __bfloat162float(__float2bfloat16(b4.w));
                uint32_t l0 = pack_bf16x2(r0, r1), l1 = pack_bf16x2(r2, r3);
                *reinterpret_cast<uint2*>(sm + A_BHI + off) = make_uint2(h0, h1);
                *reinterpret_cast<uint2*>(sm + A_BLO + off) = make_uint2(l0, l1);
            }
        }
        __syncthreads();

        float accG[8][4];
        float accB[8][4];
#pragma unroll
        for (int nt = 0; nt < 8; nt++)
#pragma unroll
            for (int j = 0; j < 4; j++) { accG[nt][j] = 0.f; accB[nt][j] = 0.f; }

#pragma unroll 2
        for (int kc = 0; kc < 8; kc++) {
            const int k0 = kc * 16 + 2 * tig;
            uint32_t aSh[4], aSl[4], aBh[4], aBl[4];
            aSh[0] = *(const uint32_t*)(sm + A_SHI + arow * DSTRIDE + k0);
            aSh[1] = *(const uint32_t*)(sm + A_SHI + (arow + 8) * DSTRIDE + k0);
            aSh[2] = *(const uint32_t*)(sm + A_SHI + arow * DSTRIDE + k0 + 8);
            aSh[3] = *(const uint32_t*)(sm + A_SHI + (arow + 8) * DSTRIDE + k0 + 8);
            aSl[0] = *(const uint32_t*)(sm + A_SLO + arow * DSTRIDE + k0);
            aSl[1] = *(const uint32_t*)(sm + A_SLO + (arow + 8) * DSTRIDE + k0);
            aSl[2] = *(const uint32_t*)(sm + A_SLO + arow * DSTRIDE + k0 + 8);
            aSl[3] = *(const uint32_t*)(sm + A_SLO + (arow + 8) * DSTRIDE + k0 + 8);
            aBh[0] = *(const uint32_t*)(sm + A_BHI + arow * DSTRIDE + k0);
            aBh[1] = *(const uint32_t*)(sm + A_BHI + (arow + 8) * DSTRIDE + k0);
            aBh[2] = *(const uint32_t*)(sm + A_BHI + arow * DSTRIDE + k0 + 8);
            aBh[3] = *(const uint32_t*)(sm + A_BHI + (arow + 8) * DSTRIDE + k0 + 8);
            aBl[0] = *(const uint32_t*)(sm + A_BLO + arow * DSTRIDE + k0);
            aBl[1] = *(const uint32_t*)(sm + A_BLO + (arow + 8) * DSTRIDE + k0);
            aBl[2] = *(const uint32_t*)(sm + A_BLO + arow * DSTRIDE + k0 + 8);
            aBl[3] = *(const uint32_t*)(sm + A_BLO + (arow + 8) * DSTRIDE + k0 + 8);

#pragma unroll
            for (int nt = 0; nt < 8; nt++) {
                const int n = ch * 64 + nt * 8 + g;
                uint32_t bh[2], bl[2];
                bh[0] = *(const uint32_t*)(wGh + n * DSTRIDE + k0);
                bh[1] = *(const uint32_t*)(wGh + n * DSTRIDE + k0 + 8);
                bl[0] = *(const uint32_t*)(wGl + n * DSTRIDE + k0);
                bl[1] = *(const uint32_t*)(wGl + n * DSTRIDE + k0 + 8);
                mma_bf16(accG[nt], aSh, bh);
                mma_bf16(accG[nt], aSl, bh);
                mma_bf16(accG[nt], aSh, bl);
                bh[0] = *(const uint32_t*)(wBh + n * DSTRIDE + k0);
                bh[1] = *(const uint32_t*)(wBh + n * DSTRIDE + k0 + 8);
                bl[0] = *(const uint32_t*)(wBl + n * DSTRIDE + k0);
                bl[1] = *(const uint32_t*)(wBl + n * DSTRIDE + k0 + 8);
                mma_bf16(accB[nt], aBh, bh);
                mma_bf16(accB[nt], aBl, bh);
                mma_bf16(accB[nt], aBh, bl);
            }
        }

        // epilogue: bias + leaky + sum, then row L2-normalize
        float sq_lo = 0.f, sq_hi = 0.f;
#pragma unroll
        for (int nt = 0; nt < 8; nt++) {
            const int col = ch * 64 + nt * 8 + 2 * tig;
            float bg0 = fbias[col], bg1 = fbias[col + 1];
            float bb0 = fbias[128 + col], bb1 = fbias[128 + col + 1];
            float x, y;
            x = accG[nt][0] + bg0; x = fmaxf(x, 0.2f * x);
            y = accB[nt][0] + bb0; y = fmaxf(y, 0.2f * y);
            accG[nt][0] = x + y; sq_lo = fmaf(accG[nt][0], accG[nt][0], sq_lo);
            x = accG[nt][1] + bg1; x = fmaxf(x, 0.2f * x);
            y = accB[nt][1] + bb1; y = fmaxf(y, 0.2f * y);
            accG[nt][1] = x + y; sq_lo = fmaf(accG[nt][1], accG[nt][1], sq_lo);
            x = accG[nt][2] + bg0; x = fmaxf(x, 0.2f * x);
            y = accB[nt][2] + bb0; y = fmaxf(y, 0.2f * y);
            accG[nt][2] = x + y; sq_hi = fmaf(accG[nt][2], accG[nt][2], sq_hi);
            x = accG[nt][3] + bg1; x = fmaxf(x, 0.2f * x);
            y = accB[nt][3] + bb1; y = fmaxf(y, 0.2f * y);
            accG[nt][3] = x + y; sq_hi = fmaf(accG[nt][3], accG[nt][3], sq_hi);
        }
#pragma unroll
        for (int m = 1; m <= 2; m <<= 1) {
            sq_lo += __shfl_xor_sync(0xffffffffu, sq_lo, m);
            sq_hi += __shfl_xor_sync(0xffffffffu, sq_hi, m);
        }
        if (tig == 0) {
            sqbuf[ch * 64 + mt * 16 + g] = sq_lo;
            sqbuf[ch * 64 + mt * 16 + g + 8] = sq_hi;
        }
        __syncthreads();
        float tot_lo = sqbuf[mt * 16 + g] + sqbuf[64 + mt * 16 + g];
        float tot_hi = sqbuf[mt * 16 + g + 8] + sqbuf[64 + mt * 16 + g + 8];
        float rn_lo = rsqrtf(fmaxf(tot_lo, 1e-12f));
        float rn_hi = rsqrtf(fmaxf(tot_hi, 1e-12f));

        const long grow_lo = row0 + mt * 16 + g;
        const long grow_hi = grow_lo + 8;
#pragma unroll
        for (int nt = 0; nt < 8; nt++) {
            const int col = ch * 64 + nt * 8 + 2 * tig;
            if (grow_lo < N_NODES) {
                float2 o = make_float2(accG[nt][0] * rn_lo, accG[nt][1] * rn_lo);
                *reinterpret_cast<float2*>(out + grow_lo * D + col) = o;
            }
            if (grow_hi < N_NODES) {
                float2 o = make_float2(accG[nt][2] * rn_hi, accG[nt][3] * rn_hi);
                *reinterpret_cast<float2*>(out + grow_hi * D + col) = o;
            }
        }
    }
}

// ------------------------- launch -------------------------
extern "C" void kernel_launch(void* const* d_in, const int* in_sizes, int n_in,
                              void* d_out, int out_size) {
    const int*   erow = (const int*)d_in[0];
    const int*   ecol = (const int*)d_in[1];
    const float* eval = (const float*)d_in[2];
    const float* ego  = (const float*)d_in[3];
    const float* wgc  = (const float*)d_in[4];
    const float* bgc  = (const float*)d_in[5];
    const float* wbi  = (const float*)d_in[6];
    const float* bbi  = (const float*)d_in[7];
    float* out = (float*)d_out;

    // 1) hist + W prep (one launch)
    histprep_kernel<<<PREP_BLOCKS + HIST_BLOCKS, 256>>>(erow, wgc, wbi);

    // 2) single-pass decoupled-lookback scan (writes start + cursor)
    scan_kernel<<<SCAN_BLOCKS, 256>>>();

    // 3) fill CSR
    fill_kernel<<<HIST_BLOCKS, 256>>>(erow, ecol, eval);

    // 4) SpMM: warp per row
    long spmm_threads = (long)N_NODES * 32;
    spmm_csr_kernel<<<(int)((spmm_threads + 255) / 256), 256>>>(ego);

    // 5) persistent dense tensor-core transform (also re-zeroes cnt/state for next call)
    cudaFuncSetAttribute(dense_mma_kernel, cudaFuncAttributeMaxDynamicSharedMemorySize, DENSE_SMEM);
    dense_mma_kernel<<<DENSE_GRID, 256, DENSE_SMEM>>>(ego, bgc, bbi, out);
}